// round 1
// baseline (speedup 1.0000x reference)
#include <cuda_runtime.h>
#include <math.h>

// Segment-sum scratch: pos_sum[b], neg_sum[b] for b < B (B = 4096 here; pad to 8192).
__device__ float g_pos_sum[8192];
__device__ float g_neg_sum[8192];

// ---------------------------------------------------------------------------
// k0: zero the scratch (must run every launch; graph replays re-use it).
// ---------------------------------------------------------------------------
__global__ void init_kernel(int n_items) {
    int i = blockIdx.x * blockDim.x + threadIdx.x;
    if (i < n_items) {
        g_pos_sum[i] = 0.0f;
        g_neg_sum[i] = 0.0f;
    }
}

// ---------------------------------------------------------------------------
// k1: warp-per-row exp(cosine) + segmented atomic accumulation.
//   a, b: [rows, 1024] fp32.  sums[row / group] += exp(cos(a_row, b_row))
// ---------------------------------------------------------------------------
__global__ void __launch_bounds__(256) row_cos_kernel(
    const float* __restrict__ a, const float* __restrict__ b,
    float* __restrict__ sums, int rows, int group)
{
    const int warp_global = (blockIdx.x * blockDim.x + threadIdx.x) >> 5;
    const int lane = threadIdx.x & 31;
    if (warp_global >= rows) return;

    const float4* __restrict__ a4 = reinterpret_cast<const float4*>(a) + (size_t)warp_global * 256;
    const float4* __restrict__ b4 = reinterpret_cast<const float4*>(b) + (size_t)warp_global * 256;

    float dot = 0.0f, na2 = 0.0f, nb2 = 0.0f;
#pragma unroll
    for (int i = 0; i < 8; i++) {
        float4 va = __ldg(a4 + lane + i * 32);
        float4 vb = __ldg(b4 + lane + i * 32);
        dot = fmaf(va.x, vb.x, dot); na2 = fmaf(va.x, va.x, na2); nb2 = fmaf(vb.x, vb.x, nb2);
        dot = fmaf(va.y, vb.y, dot); na2 = fmaf(va.y, va.y, na2); nb2 = fmaf(vb.y, vb.y, nb2);
        dot = fmaf(va.z, vb.z, dot); na2 = fmaf(va.z, va.z, na2); nb2 = fmaf(vb.z, vb.z, nb2);
        dot = fmaf(va.w, vb.w, dot); na2 = fmaf(va.w, va.w, na2); nb2 = fmaf(vb.w, vb.w, nb2);
    }
#pragma unroll
    for (int off = 16; off > 0; off >>= 1) {
        dot += __shfl_xor_sync(0xffffffffu, dot, off);
        na2 += __shfl_xor_sync(0xffffffffu, na2, off);
        nb2 += __shfl_xor_sync(0xffffffffu, nb2, off);
    }
    if (lane == 0) {
        float denom = fmaxf(sqrtf(na2) * sqrtf(nb2), 1e-8f);
        float e = expf(dot / denom);
        atomicAdd(&sums[warp_global / group], e);
    }
}

// ---------------------------------------------------------------------------
// k2: per-item loss + deterministic single-block reduction to d_out[0].
// ---------------------------------------------------------------------------
__global__ void __launch_bounds__(1024) finalize_kernel(float* __restrict__ out, int n_items) {
    __shared__ float red[32];
    float acc = 0.0f;
    for (int i = threadIdx.x; i < n_items; i += 1024) {
        float p = g_pos_sum[i];
        float n = g_neg_sum[i];
        acc += (n - p) / (p + n + 0.001f);
    }
#pragma unroll
    for (int off = 16; off > 0; off >>= 1)
        acc += __shfl_xor_sync(0xffffffffu, acc, off);
    if ((threadIdx.x & 31) == 0) red[threadIdx.x >> 5] = acc;
    __syncthreads();
    if (threadIdx.x < 32) {
        float v = red[threadIdx.x];
#pragma unroll
        for (int off = 16; off > 0; off >>= 1)
            v += __shfl_xor_sync(0xffffffffu, v, off);
        if (threadIdx.x == 0) out[0] = v;
    }
}

// ---------------------------------------------------------------------------
// Inputs (metadata order):
//   0: question_embeddings_pos  [2B, 1024] f32
//   1: question_embeddings_neg  [23B, 1024] f32
//   2: pos_image_embeddings     [2B, 1024] f32
//   3: neg_image_embeddings     [23B, 1024] f32
//   4: batch_size (int scalar, device) -- we derive B from in_sizes instead
// Output: f32 scalar.
// ---------------------------------------------------------------------------
extern "C" void kernel_launch(void* const* d_in, const int* in_sizes, int n_in,
                              void* d_out, int out_size) {
    const float* q_pos = (const float*)d_in[0];
    const float* q_neg = (const float*)d_in[1];
    const float* i_pos = (const float*)d_in[2];
    const float* i_neg = (const float*)d_in[3];
    float* out = (float*)d_out;

    const int D = 1024;
    const int B = in_sizes[0] / (2 * D);
    const int pos_rows = 2 * B;
    const int neg_rows = 23 * B;

    float* d_pos_sum; cudaGetSymbolAddress((void**)&d_pos_sum, g_pos_sum);
    float* d_neg_sum; cudaGetSymbolAddress((void**)&d_neg_sum, g_neg_sum);

    init_kernel<<<(B + 255) / 256, 256>>>(B);

    const int WPB = 8;  // warps per block (256 threads)
    row_cos_kernel<<<(pos_rows + WPB - 1) / WPB, WPB * 32>>>(q_pos, i_pos, d_pos_sum, pos_rows, 2);
    row_cos_kernel<<<(neg_rows + WPB - 1) / WPB, WPB * 32>>>(q_neg, i_neg, d_neg_sum, neg_rows, 23);

    finalize_kernel<<<1, 1024>>>(out, B);
}

// round 2
// speedup vs baseline: 1.0352x; 1.0352x over previous
#include <cuda_runtime.h>
#include <math.h>

// Per-row exp(cos) scratch. B=4096 nominal; sized for B up to 8192.
__device__ float g_epos[2 * 8192];
__device__ float g_eneg[23 * 8192];

// ---------------------------------------------------------------------------
// k1: one warp per row, covering BOTH pos (first pos_rows) and neg rows.
//     Writes exp(cosine) per row -> no atomics, no init kernel needed.
//     Thread (0,0) also zeroes out[0] for finalize's atomic accumulation
//     (stream ordering guarantees this completes before finalize runs).
// ---------------------------------------------------------------------------
__global__ void __launch_bounds__(256) row_cos_kernel(
    const float* __restrict__ q_pos, const float* __restrict__ i_pos,
    const float* __restrict__ q_neg, const float* __restrict__ i_neg,
    float* __restrict__ out, int pos_rows, int total_rows)
{
    if (blockIdx.x == 0 && threadIdx.x == 0) out[0] = 0.0f;

    const int w = (blockIdx.x * blockDim.x + threadIdx.x) >> 5;
    const int lane = threadIdx.x & 31;
    if (w >= total_rows) return;

    const float4* __restrict__ a4;
    const float4* __restrict__ b4;
    float* __restrict__ edst;
    if (w < pos_rows) {
        a4 = reinterpret_cast<const float4*>(q_pos) + (size_t)w * 256;
        b4 = reinterpret_cast<const float4*>(i_pos) + (size_t)w * 256;
        edst = &g_epos[w];
    } else {
        const int r = w - pos_rows;
        a4 = reinterpret_cast<const float4*>(q_neg) + (size_t)r * 256;
        b4 = reinterpret_cast<const float4*>(i_neg) + (size_t)r * 256;
        edst = &g_eneg[r];
    }

    float dot = 0.0f, na2 = 0.0f, nb2 = 0.0f;
#pragma unroll
    for (int i = 0; i < 8; i++) {
        float4 va = __ldg(a4 + lane + i * 32);
        float4 vb = __ldg(b4 + lane + i * 32);
        dot = fmaf(va.x, vb.x, dot); na2 = fmaf(va.x, va.x, na2); nb2 = fmaf(vb.x, vb.x, nb2);
        dot = fmaf(va.y, vb.y, dot); na2 = fmaf(va.y, va.y, na2); nb2 = fmaf(vb.y, vb.y, nb2);
        dot = fmaf(va.z, vb.z, dot); na2 = fmaf(va.z, va.z, na2); nb2 = fmaf(vb.z, vb.z, nb2);
        dot = fmaf(va.w, vb.w, dot); na2 = fmaf(va.w, va.w, na2); nb2 = fmaf(vb.w, vb.w, nb2);
    }
#pragma unroll
    for (int off = 16; off > 0; off >>= 1) {
        dot += __shfl_xor_sync(0xffffffffu, dot, off);
        na2 += __shfl_xor_sync(0xffffffffu, na2, off);
        nb2 += __shfl_xor_sync(0xffffffffu, nb2, off);
    }
    if (lane == 0) {
        float denom = fmaxf(sqrtf(na2) * sqrtf(nb2), 1e-8f);
        *edst = expf(dot / denom);
    }
}

// ---------------------------------------------------------------------------
// k2: one warp per batch item. lanes 0-1 read pos exps, lanes 2-24 read neg
//     exps, shuffle-reduce both sums, lane 0 computes the per-item loss,
//     block-reduce partials, one atomicAdd per block into out[0].
// ---------------------------------------------------------------------------
__global__ void __launch_bounds__(256) finalize_kernel(float* __restrict__ out, int n_items) {
    __shared__ float red[8];
    const int item = (blockIdx.x * blockDim.x + threadIdx.x) >> 5;
    const int lane = threadIdx.x & 31;
    const int warp_in_blk = threadIdx.x >> 5;

    float p = 0.0f, n = 0.0f;
    if (item < n_items) {
        if (lane < 2)            p = g_epos[item * 2 + lane];
        else if (lane < 25)      n = g_eneg[item * 23 + (lane - 2)];
    }
#pragma unroll
    for (int off = 16; off > 0; off >>= 1) {
        p += __shfl_xor_sync(0xffffffffu, p, off);
        n += __shfl_xor_sync(0xffffffffu, n, off);
    }
    float loss = 0.0f;
    if (lane == 0 && item < n_items)
        loss = (n - p) / (p + n + 0.001f);
    if (lane == 0) red[warp_in_blk] = loss;
    __syncthreads();
    if (threadIdx.x == 0) {
        float acc = 0.0f;
#pragma unroll
        for (int i = 0; i < 8; i++) acc += red[i];
        atomicAdd(out, acc);
    }
}

// ---------------------------------------------------------------------------
// Inputs (metadata order):
//   0: question_embeddings_pos  [2B, 1024] f32
//   1: question_embeddings_neg  [23B, 1024] f32
//   2: pos_image_embeddings     [2B, 1024] f32
//   3: neg_image_embeddings     [23B, 1024] f32
//   4: batch_size (int scalar)
// Output: f32 scalar.
// ---------------------------------------------------------------------------
extern "C" void kernel_launch(void* const* d_in, const int* in_sizes, int n_in,
                              void* d_out, int out_size) {
    const float* q_pos = (const float*)d_in[0];
    const float* q_neg = (const float*)d_in[1];
    const float* i_pos = (const float*)d_in[2];
    const float* i_neg = (const float*)d_in[3];
    float* out = (float*)d_out;

    const int D = 1024;
    const int B = in_sizes[0] / (2 * D);
    const int pos_rows = 2 * B;
    const int total_rows = 25 * B;

    const int WPB = 8;  // 256 threads / block
    row_cos_kernel<<<(total_rows + WPB - 1) / WPB, WPB * 32>>>(
        q_pos, i_pos, q_neg, i_neg, out, pos_rows, total_rows);

    finalize_kernel<<<(B + WPB - 1) / WPB, WPB * 32>>>(out, B);
}